// round 1
// baseline (speedup 1.0000x reference)
#include <cuda_runtime.h>

#define NN   20000
#define BB   4
#define DD   32
#define OUTF 64
#define SS   2
#define EE   640000
#define MM   7            // metrics
#define FF   128          // DD*BB
#define KK   224          // DD*MM

// ---------------- device scratch (no allocs allowed) ----------------
__device__ float g_x[MM][NN * FF];          // 7 x 10.24 MB
__device__ int   g_cnt[SS][NN];
__device__ int   g_fill[SS][NN];
__device__ int   g_rowptr[SS][NN + 1];
__device__ int2  g_edges[SS][EE];           // (src, val_bits) CSR-ordered

// ---------------- x0 = permute(inputs,[1,2,0]).reshape(N, D*B) ----------------
__global__ void k_transpose(const float* __restrict__ in) {
    int idx = blockIdx.x * blockDim.x + threadIdx.x;
    if (idx >= NN * FF) return;
    int n = idx >> 7;
    int r = idx & 127;
    int d = r >> 2, b = r & 3;
    g_x[0][idx] = in[((size_t)b * NN + n) * DD + d];
}

__global__ void k_zero() {
    int idx = blockIdx.x * blockDim.x + threadIdx.x;
    if (idx < SS * NN) ((int*)g_cnt)[idx] = 0;
}

__global__ void k_hist(const int* __restrict__ dst) {
    int s   = blockIdx.y;
    int idx = blockIdx.x * blockDim.x + threadIdx.x;
    if (idx < EE) atomicAdd(&g_cnt[s][dst[s * EE + idx]], 1);
}

// one block per support: chunked Hillis-Steele exclusive scan over N counters
__global__ void k_scan() {
    int s = blockIdx.x;
    __shared__ int sh[1024];
    __shared__ int carry;
    if (threadIdx.x == 0) carry = 0;
    __syncthreads();
    for (int base = 0; base < NN; base += 1024) {
        int i = base + threadIdx.x;
        int v = (i < NN) ? g_cnt[s][i] : 0;
        sh[threadIdx.x] = v;
        __syncthreads();
        for (int off = 1; off < 1024; off <<= 1) {
            int t = (threadIdx.x >= (unsigned)off) ? sh[threadIdx.x - off] : 0;
            __syncthreads();
            sh[threadIdx.x] += t;
            __syncthreads();
        }
        int excl = carry + sh[threadIdx.x] - v;   // read carry BEFORE update
        if (i < NN) { g_rowptr[s][i] = excl; g_fill[s][i] = excl; }
        __syncthreads();
        if (threadIdx.x == 0) carry += sh[1023];
        __syncthreads();
    }
    if (threadIdx.x == 0) g_rowptr[s][NN] = carry;
}

__global__ void k_scatter(const int* __restrict__ src, const int* __restrict__ dst,
                          const float* __restrict__ vals) {
    int s   = blockIdx.y;
    int idx = blockIdx.x * blockDim.x + threadIdx.x;
    if (idx >= EE) return;
    int d   = dst[s * EE + idx];
    int pos = atomicAdd(&g_fill[s][d], 1);
    g_edges[s][pos] = make_int2(src[s * EE + idx], __float_as_int(vals[s * EE + idx]));
}

// ---------------- SPMM: one warp per destination row, lane owns a float4 ----------------
// out = spmm(in)            if ci < 0
// out = 2*spmm(in) - c      otherwise
__global__ void __launch_bounds__(256) k_spmm(int ii, int ci, int oi, int s) {
    const float* __restrict__ xin = g_x[ii];
    float* __restrict__ xout      = g_x[oi];
    int gw   = (blockIdx.x * blockDim.x + threadIdx.x) >> 5;
    int lane = threadIdx.x & 31;
    if (gw >= NN) return;
    int beg = g_rowptr[s][gw], end = g_rowptr[s][gw + 1];
    const int2* __restrict__ ed = g_edges[s];
    float ax = 0.f, ay = 0.f, az = 0.f, aw = 0.f;
    int e = beg;
    int f0 = lane * 4;
    for (; e + 4 <= end; e += 4) {
        int2 e0 = ed[e], e1 = ed[e + 1], e2 = ed[e + 2], e3 = ed[e + 3];
        float4 x0 = *(const float4*)(xin + e0.x * FF + f0);
        float4 x1 = *(const float4*)(xin + e1.x * FF + f0);
        float4 x2 = *(const float4*)(xin + e2.x * FF + f0);
        float4 x3 = *(const float4*)(xin + e3.x * FF + f0);
        float v0 = __int_as_float(e0.y), v1 = __int_as_float(e1.y);
        float v2 = __int_as_float(e2.y), v3 = __int_as_float(e3.y);
        ax = fmaf(v0, x0.x, ax); ay = fmaf(v0, x0.y, ay); az = fmaf(v0, x0.z, az); aw = fmaf(v0, x0.w, aw);
        ax = fmaf(v1, x1.x, ax); ay = fmaf(v1, x1.y, ay); az = fmaf(v1, x1.z, az); aw = fmaf(v1, x1.w, aw);
        ax = fmaf(v2, x2.x, ax); ay = fmaf(v2, x2.y, ay); az = fmaf(v2, x2.z, az); aw = fmaf(v2, x2.w, aw);
        ax = fmaf(v3, x3.x, ax); ay = fmaf(v3, x3.y, ay); az = fmaf(v3, x3.z, az); aw = fmaf(v3, x3.w, aw);
    }
    for (; e < end; e++) {
        int2 e0  = ed[e];
        float4 x0 = *(const float4*)(xin + e0.x * FF + f0);
        float v0 = __int_as_float(e0.y);
        ax = fmaf(v0, x0.x, ax); ay = fmaf(v0, x0.y, ay); az = fmaf(v0, x0.z, az); aw = fmaf(v0, x0.w, aw);
    }
    float4 r;
    if (ci >= 0) {
        const float* __restrict__ cin = g_x[ci];
        float4 c = *(const float4*)(cin + gw * FF + f0);
        r.x = 2.f * ax - c.x; r.y = 2.f * ay - c.y; r.z = 2.f * az - c.z; r.w = 2.f * aw - c.w;
    } else {
        r.x = ax; r.y = ay; r.z = az; r.w = aw;
    }
    *(float4*)(xout + gw * FF + f0) = r;
}

// ---------------- final projection: y[b,n,o] = sum_{d,m} xs[m][n][d*4+b] * W[o][d*7+m] + bias[o]
#define TN        16                       // n-rows per CTA
#define XPAD      132                      // 128 + 4-float pad (bank-conflict free)
#define GEMM_SMEM ((KK * OUTF + MM * TN * XPAD + OUTF) * 4)

__global__ void __launch_bounds__(256) k_gemm(const float* __restrict__ W,
                                              const float* __restrict__ bias,
                                              float* __restrict__ out) {
    extern __shared__ float sm[];
    float* Wt  = sm;                        // [KK][OUTF], transposed
    float* xsm = sm + KK * OUTF;            // [MM][TN][XPAD]
    float* bsm = xsm + MM * TN * XPAD;      // [OUTF]
    int tid = threadIdx.x;

    for (int idx = tid; idx < KK * OUTF; idx += 256) {
        int o = idx & 63, k = idx >> 6;
        Wt[idx] = W[o * KK + k];
    }
    if (tid < OUTF) bsm[tid] = bias[tid];
    int n0 = blockIdx.x * TN;
    for (int idx = tid; idx < MM * TN * FF; idx += 256) {
        int m   = idx / (TN * FF);
        int rem = idx - m * (TN * FF);
        int nl  = rem >> 7, f = rem & 127;
        xsm[m * (TN * XPAD) + nl * XPAD + f] = g_x[m][(n0 + nl) * FF + f];
    }
    __syncthreads();

    int r  = tid >> 2;                // 0..63 : (nl, b) row
    int q  = tid & 3;                 // output quad group: o = q*16 .. q*16+15
    int nl = r >> 2, b = r & 3;
    const float* xrow = xsm + nl * XPAD + b;

    float acc[16];
#pragma unroll
    for (int j = 0; j < 16; j++) acc[j] = 0.f;

#pragma unroll 2
    for (int d = 0; d < DD; d++) {
#pragma unroll
        for (int m = 0; m < MM; m++) {
            float xv = xrow[m * (TN * XPAD) + d * 4];
            const float4* w4 = (const float4*)(Wt + (d * MM + m) * OUTF + q * 16);
            float4 wa = w4[0], wb = w4[1], wc = w4[2], wd = w4[3];
            acc[0]  = fmaf(xv, wa.x, acc[0]);  acc[1]  = fmaf(xv, wa.y, acc[1]);
            acc[2]  = fmaf(xv, wa.z, acc[2]);  acc[3]  = fmaf(xv, wa.w, acc[3]);
            acc[4]  = fmaf(xv, wb.x, acc[4]);  acc[5]  = fmaf(xv, wb.y, acc[5]);
            acc[6]  = fmaf(xv, wb.z, acc[6]);  acc[7]  = fmaf(xv, wb.w, acc[7]);
            acc[8]  = fmaf(xv, wc.x, acc[8]);  acc[9]  = fmaf(xv, wc.y, acc[9]);
            acc[10] = fmaf(xv, wc.z, acc[10]); acc[11] = fmaf(xv, wc.w, acc[11]);
            acc[12] = fmaf(xv, wd.x, acc[12]); acc[13] = fmaf(xv, wd.y, acc[13]);
            acc[14] = fmaf(xv, wd.z, acc[14]); acc[15] = fmaf(xv, wd.w, acc[15]);
        }
    }

    int n = n0 + nl;
    float* op = out + ((size_t)b * NN + n) * OUTF + q * 16;
#pragma unroll
    for (int j = 0; j < 4; j++) {
        float4 o4;
        o4.x = acc[j * 4 + 0] + bsm[q * 16 + j * 4 + 0];
        o4.y = acc[j * 4 + 1] + bsm[q * 16 + j * 4 + 1];
        o4.z = acc[j * 4 + 2] + bsm[q * 16 + j * 4 + 2];
        o4.w = acc[j * 4 + 3] + bsm[q * 16 + j * 4 + 3];
        *(float4*)(op + j * 4) = o4;
    }
}

// ---------------- launch ----------------
extern "C" void kernel_launch(void* const* d_in, const int* in_sizes, int n_in,
                              void* d_out, int out_size) {
    const float* inputs = (const float*)d_in[0];
    const float* evals  = (const float*)d_in[1];
    const float* W      = (const float*)d_in[2];
    const float* bias   = (const float*)d_in[3];
    const int*   esrc   = (const int*)d_in[4];
    const int*   edst   = (const int*)d_in[5];
    float* out = (float*)d_out;

    // build x0
    k_transpose<<<(NN * FF + 255) / 256, 256>>>(inputs);

    // build CSR for both supports
    k_zero<<<(SS * NN + 255) / 256, 256>>>();
    dim3 ge((EE + 255) / 256, SS);
    k_hist<<<ge, 256>>>(edst);
    k_scan<<<SS, 1024>>>();
    k_scatter<<<ge, 256>>>(esrc, edst, evals);

    // Chebyshev recurrence (faithful to reference aliasing: support 1 starts at xs2)
    const int spmm_grid = (NN * 32 + 255) / 256;   // 1 warp per row, 8 rows per CTA
    k_spmm<<<spmm_grid, 256>>>(0, -1, 1, 0);       // xs1 = A0 x0
    k_spmm<<<spmm_grid, 256>>>(1,  0, 2, 0);       // xs2 = 2 A0 xs1 - xs0
    k_spmm<<<spmm_grid, 256>>>(2,  1, 3, 0);       // xs3 = 2 A0 xs2 - xs1
    k_spmm<<<spmm_grid, 256>>>(2, -1, 4, 1);       // xs4 = A1 xs2
    k_spmm<<<spmm_grid, 256>>>(4,  2, 5, 1);       // xs5 = 2 A1 xs4 - xs2
    k_spmm<<<spmm_grid, 256>>>(5,  4, 6, 1);       // xs6 = 2 A1 xs5 - xs4

    // projection
    cudaFuncSetAttribute(k_gemm, cudaFuncAttributeMaxDynamicSharedMemorySize, GEMM_SMEM);
    k_gemm<<<NN / TN, 256, GEMM_SMEM>>>(W, bias, out);
}

// round 2
// speedup vs baseline: 1.0289x; 1.0289x over previous
#include <cuda_runtime.h>

#define NN   20000
#define BB   4
#define DD   32
#define OUTF 64
#define SS   2
#define EE   640000
#define MM   7            // metrics
#define FF   128          // DD*BB
#define KK   224          // DD*MM

// ---------------- device scratch (no allocs allowed) ----------------
__device__ float g_x[MM][NN * FF];          // 7 x 10.24 MB
__device__ int   g_cnt[SS][NN];
__device__ int   g_fill[SS][NN];
__device__ int   g_rowptr[SS][NN + 1];
__device__ __align__(16) int2 g_edges[SS][EE];  // (src, val_bits) CSR-ordered

// ---------------- f32x2 packed-FMA helpers (ptxas won't auto-fuse; PTX only) ----
__device__ __forceinline__ unsigned long long pk2(float lo, float hi) {
    unsigned long long r;
    asm("mov.b64 %0, {%1, %2};" : "=l"(r) : "f"(lo), "f"(hi));
    return r;
}
__device__ __forceinline__ void upk2(float& lo, float& hi, unsigned long long v) {
    asm("mov.b64 {%0, %1}, %2;" : "=f"(lo), "=f"(hi) : "l"(v));
}
__device__ __forceinline__ unsigned long long ffma2(unsigned long long a,
                                                    unsigned long long b,
                                                    unsigned long long c) {
    unsigned long long d;
    asm("fma.rn.f32x2 %0, %1, %2, %3;" : "=l"(d) : "l"(a), "l"(b), "l"(c));
    return d;
}

// ---------------- x0 transpose + counter zero (fused, independent work) -------
__global__ void k_transpose(const float* __restrict__ in) {
    int idx = blockIdx.x * blockDim.x + threadIdx.x;
    if (idx < SS * NN) ((int*)g_cnt)[idx] = 0;
    if (idx >= NN * FF) return;
    int n = idx >> 7;
    int r = idx & 127;
    int d = r >> 2, b = r & 3;
    g_x[0][idx] = in[((size_t)b * NN + n) * DD + d];
}

__global__ void k_hist(const int* __restrict__ dst) {
    int s   = blockIdx.y;
    int idx = blockIdx.x * blockDim.x + threadIdx.x;
    if (idx < EE) atomicAdd(&g_cnt[s][dst[s * EE + idx]], 1);
}

// one block of 1024 per support: thread-coarsened + warp-shuffle scan
#define SC 20   // elements per thread; 1024*20 >= 20000
__global__ void __launch_bounds__(1024) k_scan() {
    int s = blockIdx.x, t = threadIdx.x;
    int lane = t & 31, warp = t >> 5;
    int base = t * SC;
    int v[SC];
    int sum = 0;
#pragma unroll
    for (int i = 0; i < SC; i++) {
        v[i] = (base + i < NN) ? g_cnt[s][base + i] : 0;
        sum += v[i];
    }
    // inclusive warp scan of per-thread sums
    int inc = sum;
#pragma unroll
    for (int off = 1; off < 32; off <<= 1) {
        int u = __shfl_up_sync(0xffffffffu, inc, off);
        if (lane >= off) inc += u;
    }
    __shared__ int wtot[32];
    if (lane == 31) wtot[warp] = inc;
    __syncthreads();
    if (warp == 0) {
        int w = wtot[lane];
        int wi = w;
#pragma unroll
        for (int off = 1; off < 32; off <<= 1) {
            int u = __shfl_up_sync(0xffffffffu, wi, off);
            if (lane >= off) wi += u;
        }
        wtot[lane] = wi - w;    // exclusive
    }
    __syncthreads();
    int run = wtot[warp] + (inc - sum);   // exclusive prefix for this thread
#pragma unroll
    for (int i = 0; i < SC; i++) {
        if (base + i < NN) { g_rowptr[s][base + i] = run; g_fill[s][base + i] = run; }
        run += v[i];
    }
    if (t == 1023) g_rowptr[s][NN] = run;
}

__global__ void k_scatter(const int* __restrict__ src, const int* __restrict__ dst,
                          const float* __restrict__ vals) {
    int s   = blockIdx.y;
    int idx = blockIdx.x * blockDim.x + threadIdx.x;
    if (idx >= EE) return;
    int d   = dst[s * EE + idx];
    int pos = atomicAdd(&g_fill[s][d], 1);
    g_edges[s][pos] = make_int2(src[s * EE + idx], __float_as_int(vals[s * EE + idx]));
}

// ---------------- SPMM: one warp per destination row, lane owns a float4 ------
// job: out = spmm(in) if ci<0 else 2*spmm(in)-c
__device__ __forceinline__ void spmm_row(int ii, int ci, int oi, int s,
                                         int gw, int lane) {
    const float* __restrict__ xin = g_x[ii];
    float* __restrict__ xout      = g_x[oi];
    int beg = g_rowptr[s][gw], end = g_rowptr[s][gw + 1];
    const int2* __restrict__ ed = g_edges[s];
    float ax = 0.f, ay = 0.f, az = 0.f, aw = 0.f;
    int e = beg;
    int f0 = lane * 4;
    // peel to even e so int4 (2-edge) loads are 16B aligned
    if (e < end && (e & 1)) {
        int2 e0 = ed[e];
        float4 x0 = *(const float4*)(xin + e0.x * FF + f0);
        float v0 = __int_as_float(e0.y);
        ax = fmaf(v0, x0.x, ax); ay = fmaf(v0, x0.y, ay);
        az = fmaf(v0, x0.z, az); aw = fmaf(v0, x0.w, aw);
        e++;
    }
    for (; e + 8 <= end; e += 8) {
        int4 p0 = *(const int4*)(ed + e);
        int4 p1 = *(const int4*)(ed + e + 2);
        int4 p2 = *(const int4*)(ed + e + 4);
        int4 p3 = *(const int4*)(ed + e + 6);
        float4 x0 = *(const float4*)(xin + p0.x * FF + f0);
        float4 x1 = *(const float4*)(xin + p0.z * FF + f0);
        float4 x2 = *(const float4*)(xin + p1.x * FF + f0);
        float4 x3 = *(const float4*)(xin + p1.z * FF + f0);
        float4 x4 = *(const float4*)(xin + p2.x * FF + f0);
        float4 x5 = *(const float4*)(xin + p2.z * FF + f0);
        float4 x6 = *(const float4*)(xin + p3.x * FF + f0);
        float4 x7 = *(const float4*)(xin + p3.z * FF + f0);
        float v0 = __int_as_float(p0.y), v1 = __int_as_float(p0.w);
        float v2 = __int_as_float(p1.y), v3 = __int_as_float(p1.w);
        float v4 = __int_as_float(p2.y), v5 = __int_as_float(p2.w);
        float v6 = __int_as_float(p3.y), v7 = __int_as_float(p3.w);
        ax = fmaf(v0, x0.x, ax); ay = fmaf(v0, x0.y, ay); az = fmaf(v0, x0.z, az); aw = fmaf(v0, x0.w, aw);
        ax = fmaf(v1, x1.x, ax); ay = fmaf(v1, x1.y, ay); az = fmaf(v1, x1.z, az); aw = fmaf(v1, x1.w, aw);
        ax = fmaf(v2, x2.x, ax); ay = fmaf(v2, x2.y, ay); az = fmaf(v2, x2.z, az); aw = fmaf(v2, x2.w, aw);
        ax = fmaf(v3, x3.x, ax); ay = fmaf(v3, x3.y, ay); az = fmaf(v3, x3.z, az); aw = fmaf(v3, x3.w, aw);
        ax = fmaf(v4, x4.x, ax); ay = fmaf(v4, x4.y, ay); az = fmaf(v4, x4.z, az); aw = fmaf(v4, x4.w, aw);
        ax = fmaf(v5, x5.x, ax); ay = fmaf(v5, x5.y, ay); az = fmaf(v5, x5.z, az); aw = fmaf(v5, x5.w, aw);
        ax = fmaf(v6, x6.x, ax); ay = fmaf(v6, x6.y, ay); az = fmaf(v6, x6.z, az); aw = fmaf(v6, x6.w, aw);
        ax = fmaf(v7, x7.x, ax); ay = fmaf(v7, x7.y, ay); az = fmaf(v7, x7.z, az); aw = fmaf(v7, x7.w, aw);
    }
    for (; e < end; e++) {
        int2 e0  = ed[e];
        float4 x0 = *(const float4*)(xin + e0.x * FF + f0);
        float v0 = __int_as_float(e0.y);
        ax = fmaf(v0, x0.x, ax); ay = fmaf(v0, x0.y, ay);
        az = fmaf(v0, x0.z, az); aw = fmaf(v0, x0.w, aw);
    }
    float4 r;
    if (ci >= 0) {
        const float* __restrict__ cin = g_x[ci];
        float4 c = *(const float4*)(cin + gw * FF + f0);
        r.x = 2.f * ax - c.x; r.y = 2.f * ay - c.y;
        r.z = 2.f * az - c.z; r.w = 2.f * aw - c.w;
    } else {
        r.x = ax; r.y = ay; r.z = az; r.w = aw;
    }
    *(float4*)(xout + gw * FF + f0) = r;
}

__global__ void __launch_bounds__(256) k_spmm(int ii, int ci, int oi, int s) {
    int gw   = (blockIdx.x * blockDim.x + threadIdx.x) >> 5;
    int lane = threadIdx.x & 31;
    if (gw >= NN) return;
    spmm_row(ii, ci, oi, s, gw, lane);
}

// dual launch: blockIdx.y selects between two independent SPMM jobs
__global__ void __launch_bounds__(256) k_spmm2(int ii0, int ci0, int oi0, int s0,
                                               int ii1, int ci1, int oi1, int s1) {
    int gw   = (blockIdx.x * blockDim.x + threadIdx.x) >> 5;
    int lane = threadIdx.x & 31;
    if (gw >= NN) return;
    if (blockIdx.y == 0) spmm_row(ii0, ci0, oi0, s0, gw, lane);
    else                 spmm_row(ii1, ci1, oi1, s1, gw, lane);
}

// ---------------- final projection (f32x2 packed FMA) -------------------------
// y[b,n,o] = sum_{d,m} xs[m][n][d*4+b] * W[o][d*7+m] + bias[o]
#define TN        16                       // n-rows per CTA
#define XPAD      132                      // 128 + 4-float pad (bank-conflict free)
#define GEMM_SMEM ((KK * OUTF + MM * TN * XPAD + OUTF) * 4)

__global__ void __launch_bounds__(256) k_gemm(const float* __restrict__ W,
                                              const float* __restrict__ bias,
                                              float* __restrict__ out) {
    extern __shared__ float sm[];
    float* Wt  = sm;                        // [KK][OUTF], transposed (o contiguous)
    float* xsm = sm + KK * OUTF;            // [MM][TN][XPAD]
    float* bsm = xsm + MM * TN * XPAD;      // [OUTF]
    int tid = threadIdx.x;

    for (int idx = tid; idx < KK * OUTF; idx += 256) {
        int o = idx & 63, k = idx >> 6;
        Wt[idx] = W[o * KK + k];
    }
    if (tid < OUTF) bsm[tid] = bias[tid];
    int n0 = blockIdx.x * TN;
    for (int idx = tid; idx < MM * TN * FF; idx += 256) {
        int m   = idx / (TN * FF);
        int rem = idx - m * (TN * FF);
        int nl  = rem >> 7, f = rem & 127;
        xsm[m * (TN * XPAD) + nl * XPAD + f] = g_x[m][(n0 + nl) * FF + f];
    }
    __syncthreads();

    int r  = tid >> 2;                // 0..63 : (nl, b) row
    int q  = tid & 3;                 // output group: o = q*16 .. q*16+15
    int nl = r >> 2, b = r & 3;
    const float* xrow = xsm + nl * XPAD + b;

    unsigned long long acc[8];        // 8 f32x2 pairs = 16 outputs
#pragma unroll
    for (int j = 0; j < 8; j++) acc[j] = 0ull;

#pragma unroll 2
    for (int d = 0; d < DD; d++) {
#pragma unroll
        for (int m = 0; m < MM; m++) {
            float xv = xrow[m * (TN * XPAD) + d * 4];
            unsigned long long xp = pk2(xv, xv);
            const ulonglong2* w2 = (const ulonglong2*)(Wt + (d * MM + m) * OUTF + q * 16);
            ulonglong2 wa = w2[0], wb = w2[1], wc = w2[2], wd = w2[3];
            acc[0] = ffma2(xp, wa.x, acc[0]); acc[1] = ffma2(xp, wa.y, acc[1]);
            acc[2] = ffma2(xp, wb.x, acc[2]); acc[3] = ffma2(xp, wb.y, acc[3]);
            acc[4] = ffma2(xp, wc.x, acc[4]); acc[5] = ffma2(xp, wc.y, acc[5]);
            acc[6] = ffma2(xp, wd.x, acc[6]); acc[7] = ffma2(xp, wd.y, acc[7]);
        }
    }

    int n = n0 + nl;
    float* op = out + ((size_t)b * NN + n) * OUTF + q * 16;
#pragma unroll
    for (int j = 0; j < 4; j++) {
        float a0, a1, a2, a3;
        upk2(a0, a1, acc[j * 2]);
        upk2(a2, a3, acc[j * 2 + 1]);
        float4 o4;
        o4.x = a0 + bsm[q * 16 + j * 4 + 0];
        o4.y = a1 + bsm[q * 16 + j * 4 + 1];
        o4.z = a2 + bsm[q * 16 + j * 4 + 2];
        o4.w = a3 + bsm[q * 16 + j * 4 + 3];
        *(float4*)(op + j * 4) = o4;
    }
}

// ---------------- launch ----------------
extern "C" void kernel_launch(void* const* d_in, const int* in_sizes, int n_in,
                              void* d_out, int out_size) {
    const float* inputs = (const float*)d_in[0];
    const float* evals  = (const float*)d_in[1];
    const float* W      = (const float*)d_in[2];
    const float* bias   = (const float*)d_in[3];
    const int*   esrc   = (const int*)d_in[4];
    const int*   edst   = (const int*)d_in[5];
    float* out = (float*)d_out;

    // x0 build + counter zero (fused)
    k_transpose<<<(NN * FF + 255) / 256, 256>>>(inputs);

    // CSR build for both supports
    dim3 ge((EE + 255) / 256, SS);
    k_hist<<<ge, 256>>>(edst);
    k_scan<<<SS, 1024>>>();
    k_scatter<<<ge, 256>>>(esrc, edst, evals);

    // Chebyshev recurrence (faithful to reference aliasing: support 1 starts at xs2)
    const int spmm_grid = (NN * 32 + 255) / 256;   // 1 warp per row
    k_spmm<<<spmm_grid, 256>>>(0, -1, 1, 0);                       // xs1 = A0 x0
    k_spmm<<<spmm_grid, 256>>>(1,  0, 2, 0);                       // xs2 = 2 A0 xs1 - xs0
    dim3 gd(spmm_grid, 2);
    k_spmm2<<<gd, 256>>>(2, 1, 3, 0,   2, -1, 4, 1);               // xs3 ∥ xs4
    k_spmm<<<spmm_grid, 256>>>(4,  2, 5, 1);                       // xs5 = 2 A1 xs4 - xs2
    k_spmm<<<spmm_grid, 256>>>(5,  4, 6, 1);                       // xs6 = 2 A1 xs5 - xs4

    // projection
    cudaFuncSetAttribute(k_gemm, cudaFuncAttributeMaxDynamicSharedMemorySize, GEMM_SMEM);
    k_gemm<<<NN / TN, 256, GEMM_SMEM>>>(W, bias, out);
}